// round 1
// baseline (speedup 1.0000x reference)
#include <cuda_runtime.h>
#include <cstdint>

// Problem constants
#define BB 4
#define TT 1024
#define DD 1024
#define HH 16
#define HD 64
#define SC 3072
#define SF 4096   // full seq = SC + TT

// Scratch (device globals: no allocation allowed)
__device__ float g_q[(size_t)BB * HH * TT * HD];   // q, scaled by hd^-0.5, layout [b,h,t,hd]
__device__ float g_attn[(size_t)BB * TT * DD];     // attention output, layout [b,t,d]

// ---------------------------------------------------------------------------
// 128x128 SGEMM core: C(128x128) = A[M=4096,K=1024] * W[K=1024,N=1024]
// 256 threads, 8x8 per thread, BK=8.
// ---------------------------------------------------------------------------
__device__ __forceinline__ void gemm128(const float* __restrict__ A,
                                        const float* __restrict__ W,
                                        float acc[8][8])
{
    __shared__ float As[8][128];
    __shared__ float Bs[8][128];

    const int tid   = threadIdx.x;
    const int row_a = tid >> 1;          // 0..127
    const int col_a = (tid & 1) << 2;    // 0 or 4
    const int row_b = tid >> 5;          // 0..7
    const int col_b = (tid & 31) << 2;   // 0..124
    const int tx    = (tid & 15) << 3;   // 0..120
    const int ty    = (tid >> 4) << 3;   // 0..120
    const int bm    = blockIdx.y * 128;
    const int bn    = blockIdx.x * 128;

    const float* Aptr = A + (size_t)(bm + row_a) * 1024 + col_a;
    const float* Wptr = W + (size_t)row_b * 1024 + bn + col_b;

    for (int k0 = 0; k0 < 1024; k0 += 8) {
        float4 av = *(const float4*)(Aptr + k0);
        float4 wv = *(const float4*)(Wptr + (size_t)k0 * 1024);
        As[col_a + 0][row_a] = av.x;
        As[col_a + 1][row_a] = av.y;
        As[col_a + 2][row_a] = av.z;
        As[col_a + 3][row_a] = av.w;
        *(float4*)&Bs[row_b][col_b] = wv;
        __syncthreads();

        #pragma unroll
        for (int kk = 0; kk < 8; kk++) {
            float ra[8], rb[8];
            *(float4*)&ra[0] = *(const float4*)&As[kk][ty];
            *(float4*)&ra[4] = *(const float4*)&As[kk][ty + 4];
            *(float4*)&rb[0] = *(const float4*)&Bs[kk][tx];
            *(float4*)&rb[4] = *(const float4*)&Bs[kk][tx + 4];
            #pragma unroll
            for (int i = 0; i < 8; i++)
                #pragma unroll
                for (int j = 0; j < 8; j++)
                    acc[i][j] += ra[i] * rb[j];
        }
        __syncthreads();
    }
}

// ---------------------------------------------------------------------------
// QKV projections. blockIdx.z: 0 = Q (scaled, scattered to g_q),
// 1 = K (no bias, into kout rows 3072..4095), 2 = V (bias, into vout).
// ---------------------------------------------------------------------------
__global__ __launch_bounds__(256) void qkv_gemm(
    const float* __restrict__ x,
    const float* __restrict__ Wq, const float* __restrict__ Wk, const float* __restrict__ Wv,
    const float* __restrict__ bq, const float* __restrict__ bv,
    float* __restrict__ kout, float* __restrict__ vout)
{
    const float* W = (blockIdx.z == 0) ? Wq : ((blockIdx.z == 1) ? Wk : Wv);
    float acc[8][8];
    #pragma unroll
    for (int i = 0; i < 8; i++)
        #pragma unroll
        for (int j = 0; j < 8; j++) acc[i][j] = 0.0f;

    gemm128(x, W, acc);

    const int tid = threadIdx.x;
    const int tx  = (tid & 15) << 3;
    const int ty  = (tid >> 4) << 3;
    const int bm  = blockIdx.y * 128;
    const int bn  = blockIdx.x * 128;

    if (blockIdx.z == 0) {
        // Q: scale by 64^-0.5 = 0.125, scatter to [b,h,t,hd]
        #pragma unroll
        for (int i = 0; i < 8; i++) {
            int m = bm + ty + i;
            int b = m >> 10, t = m & 1023;
            #pragma unroll
            for (int jq = 0; jq < 2; jq++) {
                int n  = bn + tx + jq * 4;
                int h  = n >> 6, hd = n & 63;
                float4 bias4 = *(const float4*)&bq[n];
                float4 v;
                v.x = (acc[i][jq * 4 + 0] + bias4.x) * 0.125f;
                v.y = (acc[i][jq * 4 + 1] + bias4.y) * 0.125f;
                v.z = (acc[i][jq * 4 + 2] + bias4.z) * 0.125f;
                v.w = (acc[i][jq * 4 + 3] + bias4.w) * 0.125f;
                *(float4*)&g_q[((size_t)((b << 4) + h) * 1024 + t) * 64 + hd] = v;
            }
        }
    } else {
        float* dst = (blockIdx.z == 1) ? kout : vout;
        const bool hasb = (blockIdx.z == 2);
        #pragma unroll
        for (int i = 0; i < 8; i++) {
            int m   = bm + ty + i;
            int row = (m >> 10) * SF + SC + (m & 1023);
            #pragma unroll
            for (int jq = 0; jq < 2; jq++) {
                int n = bn + tx + jq * 4;
                float4 bias4 = hasb ? *(const float4*)&bv[n] : make_float4(0.f, 0.f, 0.f, 0.f);
                float4 v;
                v.x = acc[i][jq * 4 + 0] + bias4.x;
                v.y = acc[i][jq * 4 + 1] + bias4.y;
                v.z = acc[i][jq * 4 + 2] + bias4.z;
                v.w = acc[i][jq * 4 + 3] + bias4.w;
                *(float4*)&dst[(size_t)row * 1024 + n] = v;
            }
        }
    }
}

// ---------------------------------------------------------------------------
// Output projection: out = g_attn @ Wo + bo
// ---------------------------------------------------------------------------
__global__ __launch_bounds__(256) void o_gemm(
    const float* __restrict__ Wo, const float* __restrict__ bo, float* __restrict__ out)
{
    float acc[8][8];
    #pragma unroll
    for (int i = 0; i < 8; i++)
        #pragma unroll
        for (int j = 0; j < 8; j++) acc[i][j] = 0.0f;

    gemm128(g_attn, Wo, acc);

    const int tid = threadIdx.x;
    const int tx  = (tid & 15) << 3;
    const int ty  = (tid >> 4) << 3;
    const int bm  = blockIdx.y * 128;
    const int bn  = blockIdx.x * 128;

    #pragma unroll
    for (int i = 0; i < 8; i++) {
        int m = bm + ty + i;
        #pragma unroll
        for (int jq = 0; jq < 2; jq++) {
            int n = bn + tx + jq * 4;
            float4 bias4 = *(const float4*)&bo[n];
            float4 v;
            v.x = acc[i][jq * 4 + 0] + bias4.x;
            v.y = acc[i][jq * 4 + 1] + bias4.y;
            v.z = acc[i][jq * 4 + 2] + bias4.z;
            v.w = acc[i][jq * 4 + 3] + bias4.w;
            *(float4*)&out[(size_t)m * 1024 + n] = v;
        }
    }
}

// ---------------------------------------------------------------------------
// Copy k_cache/v_cache into first SC rows of k/v outputs (float4 vectorized)
// ---------------------------------------------------------------------------
__global__ void copy_cache(const float4* __restrict__ kc, const float4* __restrict__ vc,
                           float4* __restrict__ ko, float4* __restrict__ vo)
{
    int idx = blockIdx.x * 256 + threadIdx.x;
    const int per_b = SC * 256;           // float4 per batch
    if (idx >= BB * per_b) return;
    int b = idx / per_b;
    int r = idx - b * per_b;
    int o = b * (SF * 256) + r;
    ko[o] = kc[idx];
    vo[o] = vc[idx];
}

// ---------------------------------------------------------------------------
// Flash-style attention.
// Grid: (qtile=16, h=16, b=4); 256 threads.
// Score tile 64(q) x 64(k); thread (tx,ty) 4x4 micro-tile; online softmax.
// Mask faithful to reference: key s masked iff s < 1024 AND s > t.
// ---------------------------------------------------------------------------
__global__ __launch_bounds__(256) void attn_kernel(
    const float* __restrict__ kfull, const float* __restrict__ vfull)
{
    extern __shared__ float sm[];
    float* Qs = sm;              // [64][68], d-major: Qs[d*68+i]
    float* Ks = Qs + 64 * 68;    // [64][68], d-major: Ks[d*68+j]
    float* Vs = Ks + 64 * 68;    // [64][68], j-major: Vs[j*68+d]
    float* Ps = Vs + 64 * 68;    // [64][68], j-major: Ps[j*68+i]

    const int tid = threadIdx.x;
    const int tx  = tid & 15;
    const int ty  = tid >> 4;
    const int qi  = blockIdx.x;
    const int h   = blockIdx.y;
    const int b   = blockIdx.z;
    const int qbase = qi * 64;

    // Load Q (pre-scaled), transposed to d-major
    const float* qsrc = g_q + ((size_t)(b * HH + h) * 1024 + qbase) * 64;
    for (int idx = tid; idx < 4096; idx += 256) {
        int i = idx >> 6, d = idx & 63;
        Qs[d * 68 + i] = qsrc[idx];
    }

    float m[4], l[4], O[4][4];
    #pragma unroll
    for (int i = 0; i < 4; i++) {
        m[i] = -1e30f; l[i] = 0.0f;
        #pragma unroll
        for (int j = 0; j < 4; j++) O[i][j] = 0.0f;
    }

    const float* kb = kfull + (size_t)b * SF * 1024 + h * 64;
    const float* vb = vfull + (size_t)b * SF * 1024 + h * 64;

    for (int si = 0; si < 64; si++) {
        // Fully-masked tiles (strictly above diagonal, within first 1024 cols): skip
        if (si < 16 && si > qi) continue;
        const int sbase = si * 64;

        __syncthreads();   // previous iteration's reads of Ks/Vs/Ps complete
        // Load K (d-major) + V (j-major)
        for (int idx = tid; idx < 1024; idx += 256) {
            int j  = idx >> 4;
            int dq = (idx & 15) << 2;
            float4 kv = *(const float4*)&kb[(size_t)(sbase + j) * 1024 + dq];
            Ks[(dq + 0) * 68 + j] = kv.x;
            Ks[(dq + 1) * 68 + j] = kv.y;
            Ks[(dq + 2) * 68 + j] = kv.z;
            Ks[(dq + 3) * 68 + j] = kv.w;
            float4 vv = *(const float4*)&vb[(size_t)(sbase + j) * 1024 + dq];
            *(float4*)&Vs[j * 68 + dq] = vv;
        }
        __syncthreads();

        // Scores S = Q K^T  (4x4 per thread)
        float s[4][4];
        #pragma unroll
        for (int i = 0; i < 4; i++)
            #pragma unroll
            for (int j = 0; j < 4; j++) s[i][j] = 0.0f;

        #pragma unroll 4
        for (int d = 0; d < 64; d++) {
            float4 rq4 = *(const float4*)&Qs[d * 68 + (ty << 2)];
            float4 rk4 = *(const float4*)&Ks[d * 68 + (tx << 2)];
            float rq[4] = {rq4.x, rq4.y, rq4.z, rq4.w};
            float rk[4] = {rk4.x, rk4.y, rk4.z, rk4.w};
            #pragma unroll
            for (int i = 0; i < 4; i++)
                #pragma unroll
                for (int j = 0; j < 4; j++)
                    s[i][j] += rq[i] * rk[j];
        }

        // Diagonal tile mask: j > i (same 64-block, sbase == qbase)
        if (si == qi) {
            #pragma unroll
            for (int i = 0; i < 4; i++)
                #pragma unroll
                for (int j = 0; j < 4; j++)
                    if ((tx << 2) + j > (ty << 2) + i) s[i][j] = -1e30f;
        }

        // Online softmax (row groups = 16 consecutive lanes)
        #pragma unroll
        for (int i = 0; i < 4; i++) {
            float mt = fmaxf(fmaxf(s[i][0], s[i][1]), fmaxf(s[i][2], s[i][3]));
            mt = fmaxf(mt, __shfl_xor_sync(0xffffffffu, mt, 1));
            mt = fmaxf(mt, __shfl_xor_sync(0xffffffffu, mt, 2));
            mt = fmaxf(mt, __shfl_xor_sync(0xffffffffu, mt, 4));
            mt = fmaxf(mt, __shfl_xor_sync(0xffffffffu, mt, 8));
            float mn    = fmaxf(m[i], mt);
            float alpha = __expf(m[i] - mn);
            m[i] = mn;
            float rs = 0.0f;
            #pragma unroll
            for (int j = 0; j < 4; j++) {
                float p = __expf(s[i][j] - mn);
                s[i][j] = p;
                rs += p;
            }
            rs += __shfl_xor_sync(0xffffffffu, rs, 1);
            rs += __shfl_xor_sync(0xffffffffu, rs, 2);
            rs += __shfl_xor_sync(0xffffffffu, rs, 4);
            rs += __shfl_xor_sync(0xffffffffu, rs, 8);
            l[i] = l[i] * alpha + rs;
            #pragma unroll
            for (int d = 0; d < 4; d++) O[i][d] *= alpha;
        }

        // Stage P (j-major) for the PV GEMM
        #pragma unroll
        for (int i = 0; i < 4; i++)
            #pragma unroll
            for (int j = 0; j < 4; j++)
                Ps[((tx << 2) + j) * 68 + (ty << 2) + i] = s[i][j];
        __syncthreads();

        // O += P V
        #pragma unroll 4
        for (int j = 0; j < 64; j++) {
            float4 rp4 = *(const float4*)&Ps[j * 68 + (ty << 2)];
            float4 rv4 = *(const float4*)&Vs[j * 68 + (tx << 2)];
            float rp[4] = {rp4.x, rp4.y, rp4.z, rp4.w};
            float rv[4] = {rv4.x, rv4.y, rv4.z, rv4.w};
            #pragma unroll
            for (int i = 0; i < 4; i++)
                #pragma unroll
                for (int d = 0; d < 4; d++)
                    O[i][d] += rp[i] * rv[d];
        }
    }

    // Epilogue: normalize and write to g_attn [b,t,d]
    #pragma unroll
    for (int i = 0; i < 4; i++) {
        float inv = 1.0f / l[i];
        float4 ov;
        ov.x = O[i][0] * inv;
        ov.y = O[i][1] * inv;
        ov.z = O[i][2] * inv;
        ov.w = O[i][3] * inv;
        size_t row = (size_t)b * 1024 + qbase + (ty << 2) + i;
        *(float4*)&g_attn[row * 1024 + h * 64 + (tx << 2)] = ov;
    }
}

// ---------------------------------------------------------------------------
extern "C" void kernel_launch(void* const* d_in, const int* in_sizes, int n_in,
                              void* d_out, int out_size)
{
    const float* x  = (const float*)d_in[0];
    const float* kc = (const float*)d_in[1];
    const float* vc = (const float*)d_in[2];
    const float* Wq = (const float*)d_in[3];
    const float* bq = (const float*)d_in[4];
    const float* Wk = (const float*)d_in[5];
    const float* Wv = (const float*)d_in[6];
    const float* bv = (const float*)d_in[7];
    const float* Wo = (const float*)d_in[8];
    const float* bo = (const float*)d_in[9];

    float* out  = (float*)d_out;                         // [4,1024,1024]
    float* kout = out + (size_t)BB * TT * DD;            // [4,4096,1024]
    float* vout = kout + (size_t)BB * SF * DD;           // [4,4096,1024]

    const int attn_smem = 4 * 64 * 68 * (int)sizeof(float);  // 69632 B
    cudaFuncSetAttribute(attn_kernel, cudaFuncAttributeMaxDynamicSharedMemorySize, attn_smem);

    // 1. cache copy (independent of GEMMs)
    {
        int total = BB * SC * 256;  // float4 count
        copy_cache<<<(total + 255) / 256, 256>>>(
            (const float4*)kc, (const float4*)vc, (float4*)kout, (float4*)vout);
    }
    // 2. fused QKV projections
    qkv_gemm<<<dim3(8, 32, 3), 256>>>(x, Wq, Wk, Wv, bq, bv, kout, vout);
    // 3. attention (reads kout/vout incl. new rows)
    attn_kernel<<<dim3(16, 16, 4), 256, attn_smem>>>(kout, vout);
    // 4. output projection
    o_gemm<<<dim3(8, 32), 256>>>(Wo, bo, out);
}